// round 8
// baseline (speedup 1.0000x reference)
#include <cuda_runtime.h>
#include <math_constants.h>

#define NT   32
#define NA   64
#define NB   64
#define NGEO 128
#define N_ELEM   (NT * NA * NB * NGEO)   // 2^24
#define PLANE    N_ELEM
#define FRAME_SH 19                      // NA*NB*NGEO = 2^19
#define SCALE    10.0f
#define IDX_K    (63.0f / 20.0f)

#define TWO_PI_HI  6.2831854820251465f
#define TWO_PI_LO  (-1.7484556000744083e-7f)
#define INV_2PI    0.15915493667125702f

// Full 2x2x2 neighborhood per cell, packed as 32B (one LDG.256 per gather):
//   [0..3] = { c000, c001, c010, c011 }   (ix plane)
//   [4..7] = { c100, c101, c110, c111 }   (ix+1 plane)
// Only cells with iz in [16,47] are built (valid queries: gz in [18.9,44.1]).
// Unbuilt cells are zero (zero-initialized device global); invalid lanes read
// cell 0 (broadcast) and are masked at the end.
__device__ __align__(32) float4 g_scratch8[64 * 64 * 64 * 2];

// Build kernel over the reachable z-band only: iz0 in {16,20,...,44}.
__global__ void __launch_bounds__(256)
build_scratch_kernel(const float* __restrict__ g) {
    int tid = blockIdx.x * blockDim.x + threadIdx.x;   // 0 .. 64*64*8 - 1
    int zg  = tid & 7;
    int yx  = tid >> 3;                                // (ix<<6)|iy
    int i   = (yx << 6) | (16 + (zg << 2));            // linear cell index
    int iz0 = i & 63;
    int iy  = (i >> 6) & 63;
    int ix  = i >> 12;
    bool ztail = (iz0 + 4 < 64);

    float r00[5] = {0, 0, 0, 0, 0};
    float r01[5] = {0, 0, 0, 0, 0};
    float r10[5] = {0, 0, 0, 0, 0};
    float r11[5] = {0, 0, 0, 0, 0};

    {
        float4 a = __ldg(reinterpret_cast<const float4*>(g + i));
        r00[0] = a.x; r00[1] = a.y; r00[2] = a.z; r00[3] = a.w;
        r00[4] = ztail ? __ldg(g + i + 4) : 0.0f;
    }
    if (iy < 63) {
        float4 a = __ldg(reinterpret_cast<const float4*>(g + i + 64));
        r01[0] = a.x; r01[1] = a.y; r01[2] = a.z; r01[3] = a.w;
        r01[4] = ztail ? __ldg(g + i + 68) : 0.0f;
    }
    if (ix < 63) {
        float4 a = __ldg(reinterpret_cast<const float4*>(g + i + 4096));
        r10[0] = a.x; r10[1] = a.y; r10[2] = a.z; r10[3] = a.w;
        r10[4] = ztail ? __ldg(g + i + 4100) : 0.0f;
        if (iy < 63) {
            float4 b = __ldg(reinterpret_cast<const float4*>(g + i + 4160));
            r11[0] = b.x; r11[1] = b.y; r11[2] = b.z; r11[3] = b.w;
            r11[4] = ztail ? __ldg(g + i + 4164) : 0.0f;
        }
    }

#pragma unroll
    for (int k = 0; k < 4; k++) {
        bool zedge = (iz0 + k == 63);
        g_scratch8[(i + k) * 2 + 0] = make_float4(r00[k], zedge ? 0.f : r00[k + 1],
                                                  r01[k], zedge ? 0.f : r01[k + 1]);
        g_scratch8[(i + k) * 2 + 1] = make_float4(r10[k], zedge ? 0.f : r10[k + 1],
                                                  r11[k], zedge ? 0.f : r11[k + 1]);
    }
}

// Unconditional 256-bit gather (sm_100a): 8 corners, one instruction.
__device__ __forceinline__ void ldg256(const float4* p, float c[8]) {
    asm volatile("ld.global.nc.v8.f32 {%0,%1,%2,%3,%4,%5,%6,%7}, [%8];"
                 : "=f"(c[0]), "=f"(c[1]), "=f"(c[2]), "=f"(c[3]),
                   "=f"(c[4]), "=f"(c[5]), "=f"(c[6]), "=f"(c[7])
                 : "l"(p));
}

__global__ void __launch_bounds__(256)
grid_predictor_kernel(const float* __restrict__ t_frames,
                      const float* __restrict__ coords,
                      const float* __restrict__ Omega,
                      const float* __restrict__ t_geos,
                      const float* __restrict__ t_injection,
                      const float* __restrict__ t_start_obs,
                      float* __restrict__ out) {
    int gid  = blockIdx.x * blockDim.x + threadIdx.x;   // 8-elem chunk index
    int base = gid << 3;

    int t = base >> FRAME_SH;
    float tM   = __ldg(t_frames + t) - __ldg(t_start_obs);
    float tinj = __ldg(t_injection);

    // 10 independent stream loads, all in flight
    float4 tg[2], om[2], xv[2], yv[2], zv[2];
    tg[0] = __ldcs(reinterpret_cast<const float4*>(t_geos + base));
    tg[1] = __ldcs(reinterpret_cast<const float4*>(t_geos + base + 4));
    om[0] = __ldcs(reinterpret_cast<const float4*>(Omega  + base));
    om[1] = __ldcs(reinterpret_cast<const float4*>(Omega  + base + 4));
    xv[0] = __ldcs(reinterpret_cast<const float4*>(coords + base));
    xv[1] = __ldcs(reinterpret_cast<const float4*>(coords + base + 4));
    yv[0] = __ldcs(reinterpret_cast<const float4*>(coords + PLANE + base));
    yv[1] = __ldcs(reinterpret_cast<const float4*>(coords + PLANE + base + 4));
    zv[0] = __ldcs(reinterpret_cast<const float4*>(coords + 2 * PLANE + base));
    zv[1] = __ldcs(reinterpret_cast<const float4*>(coords + 2 * PLANE + base + 4));

    // ---- phase 1: offsets + weights for all 8 elements ----
    int   offA[8];
    float wxa[8], wya[8], wza[8];
    bool  okj[8];
#pragma unroll
    for (int j = 0; j < 8; j++) {
        int h = j >> 2, l = j & 3;
        float tgj = reinterpret_cast<const float*>(&tg[h])[l];
        float omj = reinterpret_cast<const float*>(&om[h])[l];
        float x   = reinterpret_cast<const float*>(&xv[h])[l];
        float y   = reinterpret_cast<const float*>(&yv[h])[l];
        float z   = reinterpret_cast<const float*>(&zv[h])[l];

        float trot = tM - tgj - tinj;
        float r2 = fmaf(x, x, fmaf(y, y, z * z));
        bool ok = (trot >= 0.0f) && (r2 >= 4.0f) && (r2 <= 100.0f)
                  && (fabsf(z) <= 4.0f);
        okj[j] = ok;

        float theta = -omj * trot;
        float k = rintf(theta * INV_2PI);
        float th = fmaf(-k, TWO_PI_HI, theta);
        th = fmaf(-k, TWO_PI_LO, th);
        float s, c;
        __sincosf(th, &s, &c);

        float xw = x * c - y * s;
        float yw = x * s + y * c;

        float gx = (xw + SCALE) * IDX_K;
        float gy = (yw + SCALE) * IDX_K;
        float gz = (z  + SCALE) * IDX_K;

        int ix = min(max(__float2int_rd(gx), 0), 62);
        int iy = min(max(__float2int_rd(gy), 0), 62);
        int iz = min(max(__float2int_rd(gz), 0), 63);
        wxa[j] = gx - (float)ix;
        wya[j] = gy - (float)iy;
        wza[j] = gz - (float)iz;

        // invalid -> cell 0 (zero-filled, broadcast line)
        offA[j] = ok ? (((ix << 12) | (iy << 6) | iz) << 1) : 0;
    }

    // ---- phase 2: 8 gathers in flight (one LDG.256 each) ----
    float C[8][8];
#pragma unroll
    for (int j = 0; j < 8; j++)
        ldg256(&g_scratch8[offA[j]], C[j]);

    // ---- phase 3: lerp + sigmoid + mask ----
    float r8[8];
#pragma unroll
    for (int j = 0; j < 8; j++) {
        float wz = wza[j], wy = wya[j], wx = wxa[j];
        const float* c = C[j];
        float v00 = c[0] + wz * (c[1] - c[0]);
        float v01 = c[2] + wz * (c[3] - c[2]);
        float v10 = c[4] + wz * (c[5] - c[4]);
        float v11 = c[6] + wz * (c[7] - c[6]);
        float v0  = v00 + wy * (v01 - v00);
        float v1  = v10 + wy * (v11 - v10);
        float v   = v0 + wx * (v1 - v0);
        float e   = __fdividef(1.0f, 1.0f + __expf(10.0f - v));
        r8[j] = okj[j] ? e : 0.0f;
    }

    __stcs(reinterpret_cast<float4*>(out + base),
           make_float4(r8[0], r8[1], r8[2], r8[3]));
    __stcs(reinterpret_cast<float4*>(out + base + 4),
           make_float4(r8[4], r8[5], r8[6], r8[7]));
}

extern "C" void kernel_launch(void* const* d_in, const int* in_sizes, int n_in,
                              void* d_out, int out_size) {
    const float* t_frames    = (const float*)d_in[0];
    const float* coords      = (const float*)d_in[1];
    const float* Omega       = (const float*)d_in[2];
    const float* t_geos      = (const float*)d_in[3];
    const float* t_injection = (const float*)d_in[4];
    const float* t_start_obs = (const float*)d_in[5];
    const float* grid        = (const float*)d_in[6];
    float* out               = (float*)d_out;

    build_scratch_kernel<<<(64 * 64 * 8) / 256, 256>>>(grid);

    int nthreads = N_ELEM / 8;          // 2,097,152
    int block    = 256;
    int nblk     = nthreads / block;    // 8192
    grid_predictor_kernel<<<nblk, block>>>(t_frames, coords, Omega, t_geos,
                                           t_injection, t_start_obs, out);
}